// round 14
// baseline (speedup 1.0000x reference)
#include <cuda_runtime.h>
#include <cuda_bf16.h>
#include <cuda_fp16.h>
#include <cstdint>

#define H        128
#define NE       500000
#define NN       50000
#define APAD     68                  // padded b32-pair row stride (64 + 4)

// ---------------- scratch (__device__ globals) ----------------
__device__ __align__(16) __half g_Uh[NN * H];   // U in fp16 (edge-only consumer)
__device__ __align__(16) __half g_Vh[NN * H];   // V in fp16 (edge-only consumer)
__device__ __align__(16) float g_S[NN * H];     // fp32 (RED accumulation precision)
__device__ __align__(16) float g_sumw[NN];
__device__ __align__(16) uint32_t g_B1u[32768];   // [hl][kt8][nt32][lane32][2]
__device__ __align__(16) uint32_t g_B2u[16384];   // [hl][kt8][nt16][lane32][2]

// ---------------- helpers ----------------
__device__ __forceinline__ void splitpair(float v0, float v1, uint32_t& h, uint32_t& l) {
    __nv_bfloat162 hh = __floats2bfloat162_rn(v0, v1);
    float r0 = v0 - __bfloat162float(hh.x);
    float r1 = v1 - __bfloat162float(hh.y);
    __nv_bfloat162 ll = __floats2bfloat162_rn(r0, r1);
    h = *(uint32_t*)&hh;
    l = *(uint32_t*)&ll;
}

__device__ __forceinline__ void mma_bf16(float* d,
                                         uint32_t a0, uint32_t a1, uint32_t a2, uint32_t a3,
                                         uint32_t b0, uint32_t b1) {
    asm("mma.sync.aligned.m16n8k16.row.col.f32.bf16.bf16.f32 "
        "{%0,%1,%2,%3}, {%4,%5,%6,%7}, {%8,%9}, {%0,%1,%2,%3};"
        : "+f"(d[0]), "+f"(d[1]), "+f"(d[2]), "+f"(d[3])
        : "r"(a0), "r"(a1), "r"(a2), "r"(a3), "r"(b0), "r"(b1));
}

// ---------------- zero S and sumw ----------------
__global__ void zero_kernel() {
    int i = blockIdx.x * blockDim.x + threadIdx.x;
    if (i < NN * H / 4) ((float4*)g_S)[i] = make_float4(0.f, 0.f, 0.f, 0.f);
    else if (i < NN * H / 4 + NN / 4)
        ((float4*)g_sumw)[i - NN * H / 4] = make_float4(0.f, 0.f, 0.f, 0.f);
}

// ---------------- prep: weight matrices -> bf16 hi/lo fragment images ----------------
__global__ void prep_B1(const float* __restrict__ W1) {   // [256,128]; Bcat[k][n]
    int i = blockIdx.x * blockDim.x + threadIdx.x;
    if (i >= 8192) return;
    int kt = i >> 10, nt = (i >> 5) & 31, lane = i & 31;
    int g = lane >> 2, tig = lane & 3;
    int n = nt * 8 + g;
    int k0 = kt * 16 + 2 * tig;
    float w[4];
    #pragma unroll
    for (int j = 0; j < 4; j++) {
        int k = k0 + (j >> 1) * 8 + (j & 1);
        w[j] = (n < 128) ? W1[(size_t)k * 128 + n]
                         : W1[(size_t)(128 + k) * 128 + (n - 128)];
    }
    uint32_t b0h, b0l, b1h, b1l;
    splitpair(w[0], w[1], b0h, b0l);
    splitpair(w[2], w[3], b1h, b1l);
    int base = ((kt * 32 + nt) * 32 + lane) * 2;
    g_B1u[base] = b0h; g_B1u[base + 1] = b1h;
    g_B1u[16384 + base] = b0l; g_B1u[16384 + base + 1] = b1l;
}

__global__ void prep_B2(const float* __restrict__ W2) {   // [128,128]
    int i = blockIdx.x * blockDim.x + threadIdx.x;
    if (i >= 4096) return;
    int kt = i >> 9, nt = (i >> 5) & 15, lane = i & 31;
    int g = lane >> 2, tig = lane & 3;
    int n = nt * 8 + g;
    int k0 = kt * 16 + 2 * tig;
    float w[4];
    #pragma unroll
    for (int j = 0; j < 4; j++) {
        int k = k0 + (j >> 1) * 8 + (j & 1);
        w[j] = W2[(size_t)k * 128 + n];
    }
    uint32_t b0h, b0l, b1h, b1l;
    splitpair(w[0], w[1], b0h, b0l);
    splitpair(w[2], w[3], b1h, b1l);
    int base = ((kt * 16 + nt) * 32 + lane) * 2;
    g_B2u[base] = b0h; g_B2u[base + 1] = b1h;
    g_B2u[8192 + base] = b0l; g_B2u[8192 + base + 1] = b1l;
}

// ---------------- GEMM1 (mma): U(fp16) = x@W1a + b1 ; V(fp16) = x@W1b ----------------
// grid (391, 2): blockIdx.y selects nc half (0-3 => U cols, 4-7 => V cols)
__global__ __launch_bounds__(256, 2)
void gemm1_kernel(const float* __restrict__ x, const float* __restrict__ b1) {
    extern __shared__ uint32_t sm[];
    uint32_t* sAh = sm;              // 128*68 = 8704
    uint32_t* sAl = sm + 8704;
    const int tid = threadIdx.x;
    const int rbase = blockIdx.x * 128;

    for (int i = tid; i < 128 * 32; i += 256) {
        int r = i >> 5, c4 = i & 31;
        int grow = rbase + r;
        float4 v = (grow < NN) ? ((const float4*)x)[(size_t)grow * 32 + c4]
                               : make_float4(0.f, 0.f, 0.f, 0.f);
        uint32_t h01, l01, h23, l23;
        splitpair(v.x, v.y, h01, l01);
        splitpair(v.z, v.w, h23, l23);
        *(uint2*)(sAh + r * APAD + 2 * c4) = make_uint2(h01, h23);
        *(uint2*)(sAl + r * APAD + 2 * c4) = make_uint2(l01, l23);
    }
    __syncthreads();

    const int warp = tid >> 5, lane = tid & 31, g = lane >> 2, tig = lane & 3;
    const uint32_t* a0h = sAh + (warp * 16 + g) * APAD;
    const uint32_t* a1h = sAh + (warp * 16 + g + 8) * APAD;
    const uint32_t* a0l = sAl + (warp * 16 + g) * APAD;
    const uint32_t* a1l = sAl + (warp * 16 + g + 8) * APAD;
    const int row0 = rbase + warp * 16 + g;
    const int row1 = row0 + 8;
    const uint2* gB = (const uint2*)g_B1u;   // hi [0,8192), lo [8192,16384)

    const int nc0 = blockIdx.y * 4;
    for (int nc = nc0; nc < nc0 + 4; nc++) {
        float acc[4][4] = {};
        uint2 bh[4];
        #pragma unroll
        for (int nt = 0; nt < 4; nt++)
            bh[nt] = __ldg(gB + (nc * 4 + nt) * 32 + lane);       // kt = 0
        #pragma unroll
        for (int kt = 0; kt < 8; kt++) {
            uint2 nbh[4];
            if (kt < 7) {
                #pragma unroll
                for (int nt = 0; nt < 4; nt++)
                    nbh[nt] = __ldg(gB + ((kt + 1) * 32 + nc * 4 + nt) * 32 + lane);
            }
            uint32_t ah0 = a0h[kt * 8 + tig], ah1 = a1h[kt * 8 + tig];
            uint32_t ah2 = a0h[kt * 8 + tig + 4], ah3 = a1h[kt * 8 + tig + 4];
            uint32_t al0 = a0l[kt * 8 + tig], al1 = a1l[kt * 8 + tig];
            uint32_t al2 = a0l[kt * 8 + tig + 4], al3 = a1l[kt * 8 + tig + 4];
            #pragma unroll
            for (int nt = 0; nt < 4; nt++) {
                uint2 bl = __ldg(gB + (kt * 32 + nc * 4 + nt) * 32 + lane + 8192);
                mma_bf16(acc[nt], ah0, ah1, ah2, ah3, bh[nt].x, bh[nt].y);
                mma_bf16(acc[nt], al0, al1, al2, al3, bh[nt].x, bh[nt].y);
                mma_bf16(acc[nt], ah0, ah1, ah2, ah3, bl.x, bl.y);
            }
            if (kt < 7) {
                #pragma unroll
                for (int nt = 0; nt < 4; nt++) bh[nt] = nbh[nt];
            }
        }
        #pragma unroll
        for (int nt = 0; nt < 4; nt++) {
            int ncol = (nc * 4 + nt) * 8 + 2 * tig;
            if (ncol < 128) {
                float bb0 = __ldg(b1 + ncol), bb1 = __ldg(b1 + ncol + 1);
                if (row0 < NN)
                    *(__half2*)(g_Uh + (size_t)row0 * H + ncol) =
                        __floats2half2_rn(acc[nt][0] + bb0, acc[nt][1] + bb1);
                if (row1 < NN)
                    *(__half2*)(g_Uh + (size_t)row1 * H + ncol) =
                        __floats2half2_rn(acc[nt][2] + bb0, acc[nt][3] + bb1);
            } else {
                int vc = ncol - 128;
                if (row0 < NN)
                    *(__half2*)(g_Vh + (size_t)row0 * H + vc) =
                        __floats2half2_rn(acc[nt][0], acc[nt][1]);
                if (row1 < NN)
                    *(__half2*)(g_Vh + (size_t)row1 * H + vc) =
                        __floats2half2_rn(acc[nt][2], acc[nt][3]);
            }
        }
    }
}

// ---------------- edge kernel: fp16 U + fp16 V gather, fp32 RED ----------------
__global__ __launch_bounds__(256)
void edge_kernel(const int* __restrict__ ei, const float* __restrict__ ea)
{
    const int lane = threadIdx.x & 31;
    const int gwarp = (blockIdx.x * blockDim.x + threadIdx.x) >> 5;
    const int nwarps = (gridDim.x * blockDim.x) >> 5;

    for (int e0 = gwarp * 4; e0 < NE; e0 += nwarps * 4) {
        int sn[4], dn[4]; float w[4]; uint2 up[4], vp[4];
        int cnt = (NE - e0 < 4) ? (NE - e0) : 4;
        #pragma unroll
        for (int j = 0; j < 4; j++) {
            int e = e0 + j;
            if (j < cnt) { sn[j] = __ldg(ei + e); dn[j] = __ldg(ei + NE + e); w[j] = __ldg(ea + e); }
            else { sn[j] = 0; dn[j] = 0; w[j] = 0.f; }
        }
        #pragma unroll
        for (int j = 0; j < 4; j++) {
            up[j] = *(const uint2*)(g_Uh + (size_t)sn[j] * H + 4 * lane);
            vp[j] = *(const uint2*)(g_Vh + (size_t)dn[j] * H + 4 * lane);
        }
        #pragma unroll
        for (int j = 0; j < 4; j++) {
            if (j < cnt) {
                float2 u0 = __half22float2(*(__half2*)&up[j].x);
                float2 u1 = __half22float2(*(__half2*)&up[j].y);
                float2 v0 = __half22float2(*(__half2*)&vp[j].x);
                float2 v1 = __half22float2(*(__half2*)&vp[j].y);
                float a0 = fmaxf(u0.x + v0.x, 0.f) * w[j];
                float a1 = fmaxf(u0.y + v0.y, 0.f) * w[j];
                float a2 = fmaxf(u1.x + v1.x, 0.f) * w[j];
                float a3 = fmaxf(u1.y + v1.y, 0.f) * w[j];
                float* p = g_S + (size_t)dn[j] * H + 4 * lane;
                asm volatile("red.global.add.v4.f32 [%0], {%1,%2,%3,%4};"
                             :: "l"(p), "f"(a0), "f"(a1), "f"(a2), "f"(a3) : "memory");
                if (lane == 0)
                    asm volatile("red.global.add.f32 [%0], %1;"
                                 :: "l"(g_sumw + dn[j]), "f"(w[j]) : "memory");
            }
        }
    }
}

// ---------------- GEMM2 (mma): out = x + S@W2 + b2*sumw ----------------
// grid (391, 2): blockIdx.y selects nc half
__global__ __launch_bounds__(256, 2)
void gemm2_kernel(const float* __restrict__ x, const float* __restrict__ b2,
                  float* __restrict__ out) {
    extern __shared__ uint32_t sm[];
    uint32_t* sAh = sm;               // 128*68 = 8704
    uint32_t* sAl = sm + 8704;
    const int tid = threadIdx.x;
    const int rbase = blockIdx.x * 128;

    for (int i = tid; i < 128 * 32; i += 256) {
        int r = i >> 5, c4 = i & 31;
        int grow = rbase + r;
        float4 v = (grow < NN) ? ((const float4*)g_S)[(size_t)grow * 32 + c4]
                               : make_float4(0.f, 0.f, 0.f, 0.f);
        uint32_t h01, l01, h23, l23;
        splitpair(v.x, v.y, h01, l01);
        splitpair(v.z, v.w, h23, l23);
        *(uint2*)(sAh + r * APAD + 2 * c4) = make_uint2(h01, h23);
        *(uint2*)(sAl + r * APAD + 2 * c4) = make_uint2(l01, l23);
    }
    __syncthreads();

    const int warp = tid >> 5, lane = tid & 31, g = lane >> 2, tig = lane & 3;
    const uint32_t* a0h = sAh + (warp * 16 + g) * APAD;
    const uint32_t* a1h = sAh + (warp * 16 + g + 8) * APAD;
    const uint32_t* a0l = sAl + (warp * 16 + g) * APAD;
    const uint32_t* a1l = sAl + (warp * 16 + g + 8) * APAD;
    const int row0 = rbase + warp * 16 + g;
    const int row1 = row0 + 8;
    const float sw0 = (row0 < NN) ? g_sumw[row0] : 0.f;
    const float sw1 = (row1 < NN) ? g_sumw[row1] : 0.f;
    const uint2* gB = (const uint2*)g_B2u;   // hi [0,4096), lo [4096,8192)

    const int nc0 = blockIdx.y * 2;
    for (int nc = nc0; nc < nc0 + 2; nc++) {
        float acc[4][4] = {};
        uint2 bh[4];
        #pragma unroll
        for (int nt = 0; nt < 4; nt++)
            bh[nt] = __ldg(gB + (nc * 4 + nt) * 32 + lane);       // kt = 0
        #pragma unroll
        for (int kt = 0; kt < 8; kt++) {
            uint2 nbh[4];
            if (kt < 7) {
                #pragma unroll
                for (int nt = 0; nt < 4; nt++)
                    nbh[nt] = __ldg(gB + ((kt + 1) * 16 + nc * 4 + nt) * 32 + lane);
            }
            uint32_t ah0 = a0h[kt * 8 + tig], ah1 = a1h[kt * 8 + tig];
            uint32_t ah2 = a0h[kt * 8 + tig + 4], ah3 = a1h[kt * 8 + tig + 4];
            uint32_t al0 = a0l[kt * 8 + tig], al1 = a1l[kt * 8 + tig];
            uint32_t al2 = a0l[kt * 8 + tig + 4], al3 = a1l[kt * 8 + tig + 4];
            #pragma unroll
            for (int nt = 0; nt < 4; nt++) {
                uint2 bl = __ldg(gB + (kt * 16 + nc * 4 + nt) * 32 + lane + 4096);
                mma_bf16(acc[nt], ah0, ah1, ah2, ah3, bh[nt].x, bh[nt].y);
                mma_bf16(acc[nt], al0, al1, al2, al3, bh[nt].x, bh[nt].y);
                mma_bf16(acc[nt], ah0, ah1, ah2, ah3, bl.x, bl.y);
            }
            if (kt < 7) {
                #pragma unroll
                for (int nt = 0; nt < 4; nt++) bh[nt] = nbh[nt];
            }
        }
        #pragma unroll
        for (int nt = 0; nt < 4; nt++) {
            int ncol = (nc * 4 + nt) * 8 + 2 * tig;
            float bb0 = __ldg(b2 + ncol), bb1 = __ldg(b2 + ncol + 1);
            if (row0 < NN) {
                float2 xr = *(const float2*)(x + (size_t)row0 * H + ncol);
                *(float2*)(out + (size_t)row0 * H + ncol) =
                    make_float2(xr.x + acc[nt][0] + bb0 * sw0,
                                xr.y + acc[nt][1] + bb1 * sw0);
            }
            if (row1 < NN) {
                float2 xr = *(const float2*)(x + (size_t)row1 * H + ncol);
                *(float2*)(out + (size_t)row1 * H + ncol) =
                    make_float2(xr.x + acc[nt][2] + bb0 * sw1,
                                xr.y + acc[nt][3] + bb1 * sw1);
            }
        }
    }
}

// ---------------- launch ----------------
extern "C" void kernel_launch(void* const* d_in, const int* in_sizes, int n_in,
                              void* d_out, int out_size) {
    (void)in_sizes; (void)n_in; (void)out_size;
    const float* x  = (const float*)d_in[0];
    const int*   ei = (const int*)d_in[1];
    const float* ea = (const float*)d_in[2];
    const float* W1 = (const float*)d_in[3];
    const float* b1 = (const float*)d_in[4];
    const float* W2 = (const float*)d_in[5];
    const float* b2 = (const float*)d_in[6];
    float* out = (float*)d_out;

    const int nz = NN * H / 4 + NN / 4;
    zero_kernel<<<(nz + 255) / 256, 256>>>();
    prep_B1<<<32, 256>>>(W1);
    prep_B2<<<16, 256>>>(W2);

    const size_t smemA = (size_t)(2 * 8704) * 4;        // 68 KB (A hi/lo)
    cudaFuncSetAttribute(gemm1_kernel, cudaFuncAttributeMaxDynamicSharedMemorySize, (int)smemA);
    dim3 grid1((NN + 127) / 128, 2);
    gemm1_kernel<<<grid1, 256, smemA>>>(x, b1);   // launch #4 -> profiled

    edge_kernel<<<2048, 256>>>(ei, ea);

    cudaFuncSetAttribute(gemm2_kernel, cudaFuncAttributeMaxDynamicSharedMemorySize, (int)smemA);
    dim3 grid2((NN + 127) / 128, 2);
    gemm2_kernel<<<grid2, 256, smemA>>>(x, b2, out);
}

// round 15
// speedup vs baseline: 1.0698x; 1.0698x over previous
#include <cuda_runtime.h>
#include <cuda_bf16.h>
#include <cuda_fp16.h>
#include <cstdint>

#define H        128
#define NE       500000
#define NN       50000
#define APAD     68                  // padded b32-pair row stride (64 + 4)

// ---------------- scratch (__device__ globals) ----------------
__device__ __align__(16) __half g_Uh[NN * H];   // U in fp16 (edge-only consumer)
__device__ __align__(16) __half g_Vh[NN * H];   // V in fp16 (edge-only consumer)
__device__ __align__(16) float g_S[NN * H];     // fp32 (RED accumulation precision)
__device__ __align__(16) float g_sumw[NN];
__device__ __align__(16) uint32_t g_B1u[32768];   // [hl][kt8][nt32][lane32][2]
__device__ __align__(16) uint32_t g_B2u[16384];   // [hl][kt8][nt16][lane32][2]

// ---------------- helpers ----------------
__device__ __forceinline__ void splitpair(float v0, float v1, uint32_t& h, uint32_t& l) {
    __nv_bfloat162 hh = __floats2bfloat162_rn(v0, v1);
    float r0 = v0 - __bfloat162float(hh.x);
    float r1 = v1 - __bfloat162float(hh.y);
    __nv_bfloat162 ll = __floats2bfloat162_rn(r0, r1);
    h = *(uint32_t*)&hh;
    l = *(uint32_t*)&ll;
}

__device__ __forceinline__ void mma_bf16(float* d,
                                         uint32_t a0, uint32_t a1, uint32_t a2, uint32_t a3,
                                         uint32_t b0, uint32_t b1) {
    asm("mma.sync.aligned.m16n8k16.row.col.f32.bf16.bf16.f32 "
        "{%0,%1,%2,%3}, {%4,%5,%6,%7}, {%8,%9}, {%0,%1,%2,%3};"
        : "+f"(d[0]), "+f"(d[1]), "+f"(d[2]), "+f"(d[3])
        : "r"(a0), "r"(a1), "r"(a2), "r"(a3), "r"(b0), "r"(b1));
}

// ---------------- zero S and sumw ----------------
__global__ void zero_kernel() {
    int i = blockIdx.x * blockDim.x + threadIdx.x;
    if (i < NN * H / 4) ((float4*)g_S)[i] = make_float4(0.f, 0.f, 0.f, 0.f);
    else if (i < NN * H / 4 + NN / 4)
        ((float4*)g_sumw)[i - NN * H / 4] = make_float4(0.f, 0.f, 0.f, 0.f);
}

// ---------------- prep: weight matrices -> bf16 hi/lo fragment images ----------------
__global__ void prep_B1(const float* __restrict__ W1) {   // [256,128]; Bcat[k][n]
    int i = blockIdx.x * blockDim.x + threadIdx.x;
    if (i >= 8192) return;
    int kt = i >> 10, nt = (i >> 5) & 31, lane = i & 31;
    int g = lane >> 2, tig = lane & 3;
    int n = nt * 8 + g;
    int k0 = kt * 16 + 2 * tig;
    float w[4];
    #pragma unroll
    for (int j = 0; j < 4; j++) {
        int k = k0 + (j >> 1) * 8 + (j & 1);
        w[j] = (n < 128) ? W1[(size_t)k * 128 + n]
                         : W1[(size_t)(128 + k) * 128 + (n - 128)];
    }
    uint32_t b0h, b0l, b1h, b1l;
    splitpair(w[0], w[1], b0h, b0l);
    splitpair(w[2], w[3], b1h, b1l);
    int base = ((kt * 32 + nt) * 32 + lane) * 2;
    g_B1u[base] = b0h; g_B1u[base + 1] = b1h;
    g_B1u[16384 + base] = b0l; g_B1u[16384 + base + 1] = b1l;
}

__global__ void prep_B2(const float* __restrict__ W2) {   // [128,128]
    int i = blockIdx.x * blockDim.x + threadIdx.x;
    if (i >= 4096) return;
    int kt = i >> 9, nt = (i >> 5) & 15, lane = i & 31;
    int g = lane >> 2, tig = lane & 3;
    int n = nt * 8 + g;
    int k0 = kt * 16 + 2 * tig;
    float w[4];
    #pragma unroll
    for (int j = 0; j < 4; j++) {
        int k = k0 + (j >> 1) * 8 + (j & 1);
        w[j] = W2[(size_t)k * 128 + n];
    }
    uint32_t b0h, b0l, b1h, b1l;
    splitpair(w[0], w[1], b0h, b0l);
    splitpair(w[2], w[3], b1h, b1l);
    int base = ((kt * 16 + nt) * 32 + lane) * 2;
    g_B2u[base] = b0h; g_B2u[base + 1] = b1h;
    g_B2u[8192 + base] = b0l; g_B2u[8192 + base + 1] = b1l;
}

// ---------------- GEMM1 (mma): U(fp16) = x@W1a + b1 ; V(fp16) = x@W1b ----------------
// 8 warps x 16 rows = 128 rows per CTA; N = 256; bh prefetched, bl on demand (R13 form)
__global__ __launch_bounds__(256, 2)
void gemm1_kernel(const float* __restrict__ x, const float* __restrict__ b1) {
    extern __shared__ uint32_t sm[];
    uint32_t* sAh = sm;              // 128*68 = 8704
    uint32_t* sAl = sm + 8704;
    const int tid = threadIdx.x;
    const int rbase = blockIdx.x * 128;

    for (int i = tid; i < 128 * 32; i += 256) {
        int r = i >> 5, c4 = i & 31;
        int grow = rbase + r;
        float4 v = (grow < NN) ? ((const float4*)x)[(size_t)grow * 32 + c4]
                               : make_float4(0.f, 0.f, 0.f, 0.f);
        uint32_t h01, l01, h23, l23;
        splitpair(v.x, v.y, h01, l01);
        splitpair(v.z, v.w, h23, l23);
        *(uint2*)(sAh + r * APAD + 2 * c4) = make_uint2(h01, h23);
        *(uint2*)(sAl + r * APAD + 2 * c4) = make_uint2(l01, l23);
    }
    __syncthreads();

    const int warp = tid >> 5, lane = tid & 31, g = lane >> 2, tig = lane & 3;
    const uint32_t* a0h = sAh + (warp * 16 + g) * APAD;
    const uint32_t* a1h = sAh + (warp * 16 + g + 8) * APAD;
    const uint32_t* a0l = sAl + (warp * 16 + g) * APAD;
    const uint32_t* a1l = sAl + (warp * 16 + g + 8) * APAD;
    const int row0 = rbase + warp * 16 + g;
    const int row1 = row0 + 8;
    const uint2* gB = (const uint2*)g_B1u;   // hi [0,8192), lo [8192,16384)

    for (int nc = 0; nc < 8; nc++) {
        float acc[4][4] = {};
        uint2 bh[4];
        #pragma unroll
        for (int nt = 0; nt < 4; nt++)
            bh[nt] = __ldg(gB + (nc * 4 + nt) * 32 + lane);       // kt = 0
        #pragma unroll
        for (int kt = 0; kt < 8; kt++) {
            uint2 nbh[4];
            if (kt < 7) {
                #pragma unroll
                for (int nt = 0; nt < 4; nt++)
                    nbh[nt] = __ldg(gB + ((kt + 1) * 32 + nc * 4 + nt) * 32 + lane);
            }
            uint32_t ah0 = a0h[kt * 8 + tig], ah1 = a1h[kt * 8 + tig];
            uint32_t ah2 = a0h[kt * 8 + tig + 4], ah3 = a1h[kt * 8 + tig + 4];
            uint32_t al0 = a0l[kt * 8 + tig], al1 = a1l[kt * 8 + tig];
            uint32_t al2 = a0l[kt * 8 + tig + 4], al3 = a1l[kt * 8 + tig + 4];
            #pragma unroll
            for (int nt = 0; nt < 4; nt++) {
                uint2 bl = __ldg(gB + (kt * 32 + nc * 4 + nt) * 32 + lane + 8192);
                mma_bf16(acc[nt], ah0, ah1, ah2, ah3, bh[nt].x, bh[nt].y);
                mma_bf16(acc[nt], al0, al1, al2, al3, bh[nt].x, bh[nt].y);
                mma_bf16(acc[nt], ah0, ah1, ah2, ah3, bl.x, bl.y);
            }
            if (kt < 7) {
                #pragma unroll
                for (int nt = 0; nt < 4; nt++) bh[nt] = nbh[nt];
            }
        }
        #pragma unroll
        for (int nt = 0; nt < 4; nt++) {
            int ncol = (nc * 4 + nt) * 8 + 2 * tig;
            if (ncol < 128) {
                float bb0 = __ldg(b1 + ncol), bb1 = __ldg(b1 + ncol + 1);
                if (row0 < NN)
                    *(__half2*)(g_Uh + (size_t)row0 * H + ncol) =
                        __floats2half2_rn(acc[nt][0] + bb0, acc[nt][1] + bb1);
                if (row1 < NN)
                    *(__half2*)(g_Uh + (size_t)row1 * H + ncol) =
                        __floats2half2_rn(acc[nt][2] + bb0, acc[nt][3] + bb1);
            } else {
                int vc = ncol - 128;
                if (row0 < NN)
                    *(__half2*)(g_Vh + (size_t)row0 * H + vc) =
                        __floats2half2_rn(acc[nt][0], acc[nt][1]);
                if (row1 < NN)
                    *(__half2*)(g_Vh + (size_t)row1 * H + vc) =
                        __floats2half2_rn(acc[nt][2], acc[nt][3]);
            }
        }
    }
}

// ---------------- edge kernel: fp16 U + fp16 V gather, fp32 RED ----------------
__global__ __launch_bounds__(256)
void edge_kernel(const int* __restrict__ ei, const float* __restrict__ ea)
{
    const int lane = threadIdx.x & 31;
    const int gwarp = (blockIdx.x * blockDim.x + threadIdx.x) >> 5;
    const int nwarps = (gridDim.x * blockDim.x) >> 5;

    for (int e0 = gwarp * 4; e0 < NE; e0 += nwarps * 4) {
        int sn[4], dn[4]; float w[4]; uint2 up[4], vp[4];
        int cnt = (NE - e0 < 4) ? (NE - e0) : 4;
        #pragma unroll
        for (int j = 0; j < 4; j++) {
            int e = e0 + j;
            if (j < cnt) { sn[j] = __ldg(ei + e); dn[j] = __ldg(ei + NE + e); w[j] = __ldg(ea + e); }
            else { sn[j] = 0; dn[j] = 0; w[j] = 0.f; }
        }
        #pragma unroll
        for (int j = 0; j < 4; j++) {
            up[j] = *(const uint2*)(g_Uh + (size_t)sn[j] * H + 4 * lane);
            vp[j] = *(const uint2*)(g_Vh + (size_t)dn[j] * H + 4 * lane);
        }
        #pragma unroll
        for (int j = 0; j < 4; j++) {
            if (j < cnt) {
                float2 u0 = __half22float2(*(__half2*)&up[j].x);
                float2 u1 = __half22float2(*(__half2*)&up[j].y);
                float2 v0 = __half22float2(*(__half2*)&vp[j].x);
                float2 v1 = __half22float2(*(__half2*)&vp[j].y);
                float a0 = fmaxf(u0.x + v0.x, 0.f) * w[j];
                float a1 = fmaxf(u0.y + v0.y, 0.f) * w[j];
                float a2 = fmaxf(u1.x + v1.x, 0.f) * w[j];
                float a3 = fmaxf(u1.y + v1.y, 0.f) * w[j];
                float* p = g_S + (size_t)dn[j] * H + 4 * lane;
                asm volatile("red.global.add.v4.f32 [%0], {%1,%2,%3,%4};"
                             :: "l"(p), "f"(a0), "f"(a1), "f"(a2), "f"(a3) : "memory");
                if (lane == 0)
                    asm volatile("red.global.add.f32 [%0], %1;"
                                 :: "l"(g_sumw + dn[j]), "f"(w[j]) : "memory");
            }
        }
    }
}

// ---------------- GEMM2 (mma): out = x + S@W2 + b2*sumw (R13 form) ----------------
__global__ __launch_bounds__(256, 2)
void gemm2_kernel(const float* __restrict__ x, const float* __restrict__ b2,
                  float* __restrict__ out) {
    extern __shared__ uint32_t sm[];
    uint32_t* sAh = sm;               // 128*68 = 8704
    uint32_t* sAl = sm + 8704;
    const int tid = threadIdx.x;
    const int rbase = blockIdx.x * 128;

    for (int i = tid; i < 128 * 32; i += 256) {
        int r = i >> 5, c4 = i & 31;
        int grow = rbase + r;
        float4 v = (grow < NN) ? ((const float4*)g_S)[(size_t)grow * 32 + c4]
                               : make_float4(0.f, 0.f, 0.f, 0.f);
        uint32_t h01, l01, h23, l23;
        splitpair(v.x, v.y, h01, l01);
        splitpair(v.z, v.w, h23, l23);
        *(uint2*)(sAh + r * APAD + 2 * c4) = make_uint2(h01, h23);
        *(uint2*)(sAl + r * APAD + 2 * c4) = make_uint2(l01, l23);
    }
    __syncthreads();

    const int warp = tid >> 5, lane = tid & 31, g = lane >> 2, tig = lane & 3;
    const uint32_t* a0h = sAh + (warp * 16 + g) * APAD;
    const uint32_t* a1h = sAh + (warp * 16 + g + 8) * APAD;
    const uint32_t* a0l = sAl + (warp * 16 + g) * APAD;
    const uint32_t* a1l = sAl + (warp * 16 + g + 8) * APAD;
    const int row0 = rbase + warp * 16 + g;
    const int row1 = row0 + 8;
    const float sw0 = (row0 < NN) ? g_sumw[row0] : 0.f;
    const float sw1 = (row1 < NN) ? g_sumw[row1] : 0.f;
    const uint2* gB = (const uint2*)g_B2u;   // hi [0,4096), lo [4096,8192)

    for (int nc = 0; nc < 4; nc++) {
        float acc[4][4] = {};
        uint2 bh[4];
        #pragma unroll
        for (int nt = 0; nt < 4; nt++)
            bh[nt] = __ldg(gB + (nc * 4 + nt) * 32 + lane);       // kt = 0
        #pragma unroll
        for (int kt = 0; kt < 8; kt++) {
            uint2 nbh[4];
            if (kt < 7) {
                #pragma unroll
                for (int nt = 0; nt < 4; nt++)
                    nbh[nt] = __ldg(gB + ((kt + 1) * 16 + nc * 4 + nt) * 32 + lane);
            }
            uint32_t ah0 = a0h[kt * 8 + tig], ah1 = a1h[kt * 8 + tig];
            uint32_t ah2 = a0h[kt * 8 + tig + 4], ah3 = a1h[kt * 8 + tig + 4];
            uint32_t al0 = a0l[kt * 8 + tig], al1 = a1l[kt * 8 + tig];
            uint32_t al2 = a0l[kt * 8 + tig + 4], al3 = a1l[kt * 8 + tig + 4];
            #pragma unroll
            for (int nt = 0; nt < 4; nt++) {
                uint2 bl = __ldg(gB + (kt * 16 + nc * 4 + nt) * 32 + lane + 4096);
                mma_bf16(acc[nt], ah0, ah1, ah2, ah3, bh[nt].x, bh[nt].y);
                mma_bf16(acc[nt], al0, al1, al2, al3, bh[nt].x, bh[nt].y);
                mma_bf16(acc[nt], ah0, ah1, ah2, ah3, bl.x, bl.y);
            }
            if (kt < 7) {
                #pragma unroll
                for (int nt = 0; nt < 4; nt++) bh[nt] = nbh[nt];
            }
        }
        #pragma unroll
        for (int nt = 0; nt < 4; nt++) {
            int ncol = (nc * 4 + nt) * 8 + 2 * tig;
            float bb0 = __ldg(b2 + ncol), bb1 = __ldg(b2 + ncol + 1);
            if (row0 < NN) {
                float2 xr = *(const float2*)(x + (size_t)row0 * H + ncol);
                *(float2*)(out + (size_t)row0 * H + ncol) =
                    make_float2(xr.x + acc[nt][0] + bb0 * sw0,
                                xr.y + acc[nt][1] + bb1 * sw0);
            }
            if (row1 < NN) {
                float2 xr = *(const float2*)(x + (size_t)row1 * H + ncol);
                *(float2*)(out + (size_t)row1 * H + ncol) =
                    make_float2(xr.x + acc[nt][2] + bb0 * sw1,
                                xr.y + acc[nt][3] + bb1 * sw1);
            }
        }
    }
}

// ---------------- launch ----------------
extern "C" void kernel_launch(void* const* d_in, const int* in_sizes, int n_in,
                              void* d_out, int out_size) {
    (void)in_sizes; (void)n_in; (void)out_size;
    const float* x  = (const float*)d_in[0];
    const int*   ei = (const int*)d_in[1];
    const float* ea = (const float*)d_in[2];
    const float* W1 = (const float*)d_in[3];
    const float* b1 = (const float*)d_in[4];
    const float* W2 = (const float*)d_in[5];
    const float* b2 = (const float*)d_in[6];
    float* out = (float*)d_out;

    const int nz = NN * H / 4 + NN / 4;
    zero_kernel<<<(nz + 255) / 256, 256>>>();
    prep_B1<<<32, 256>>>(W1);
    prep_B2<<<16, 256>>>(W2);

    const size_t smemA = (size_t)(2 * 8704) * 4;        // 68 KB (A hi/lo)
    cudaFuncSetAttribute(gemm1_kernel, cudaFuncAttributeMaxDynamicSharedMemorySize, (int)smemA);
    gemm1_kernel<<<(NN + 127) / 128, 256, smemA>>>(x, b1);   // launch #4 -> profiled

    edge_kernel<<<2048, 256>>>(ei, ea);

    cudaFuncSetAttribute(gemm2_kernel, cudaFuncAttributeMaxDynamicSharedMemorySize, (int)smemA);
    gemm2_kernel<<<(NN + 127) / 128, 256, smemA>>>(x, b2, out);
}

// round 16
// speedup vs baseline: 1.1661x; 1.0901x over previous
#include <cuda_runtime.h>
#include <cuda_fp16.h>
#include <cstdint>

#define H        128
#define NE       500000
#define NN       50000
#define APAD     68                  // padded b32-pair row stride (64 + 4)

// ---------------- scratch (__device__ globals) ----------------
__device__ __align__(16) __half g_Uh[NN * H];   // U in fp16 (edge-only consumer)
__device__ __align__(16) __half g_Vh[NN * H];   // V in fp16 (edge-only consumer)
__device__ __align__(16) float g_S[NN * H];     // fp32 (RED accumulation precision)
__device__ __align__(16) float g_sumw[NN];
__device__ __align__(16) uint32_t g_B1u[16384];   // fp16 hi frags [kt8][nt32][lane32][2]
__device__ __align__(16) uint32_t g_B2u[8192];    // fp16 hi frags [kt8][nt16][lane32][2]

// ---------------- helpers ----------------
__device__ __forceinline__ uint32_t packh2(float v0, float v1) {
    __half2 hh = __floats2half2_rn(v0, v1);
    return *(uint32_t*)&hh;
}
__device__ __forceinline__ void splitpairh(float v0, float v1, uint32_t& h, uint32_t& l) {
    __half2 hh = __floats2half2_rn(v0, v1);
    float2 hf = __half22float2(hh);
    __half2 ll = __floats2half2_rn(v0 - hf.x, v1 - hf.y);
    h = *(uint32_t*)&hh;
    l = *(uint32_t*)&ll;
}

__device__ __forceinline__ void mma_f16(float* d,
                                        uint32_t a0, uint32_t a1, uint32_t a2, uint32_t a3,
                                        uint32_t b0, uint32_t b1) {
    asm("mma.sync.aligned.m16n8k16.row.col.f32.f16.f16.f32 "
        "{%0,%1,%2,%3}, {%4,%5,%6,%7}, {%8,%9}, {%0,%1,%2,%3};"
        : "+f"(d[0]), "+f"(d[1]), "+f"(d[2]), "+f"(d[3])
        : "r"(a0), "r"(a1), "r"(a2), "r"(a3), "r"(b0), "r"(b1));
}

// ---------------- zero S and sumw ----------------
__global__ void zero_kernel() {
    int i = blockIdx.x * blockDim.x + threadIdx.x;
    if (i < NN * H / 4) ((float4*)g_S)[i] = make_float4(0.f, 0.f, 0.f, 0.f);
    else if (i < NN * H / 4 + NN / 4)
        ((float4*)g_sumw)[i - NN * H / 4] = make_float4(0.f, 0.f, 0.f, 0.f);
}

// ---------------- prep: weight matrices -> fp16 fragment images ----------------
__global__ void prep_B1(const float* __restrict__ W1) {   // [256,128]; Bcat[k][n]
    int i = blockIdx.x * blockDim.x + threadIdx.x;
    if (i >= 8192) return;
    int kt = i >> 10, nt = (i >> 5) & 31, lane = i & 31;
    int g = lane >> 2, tig = lane & 3;
    int n = nt * 8 + g;
    int k0 = kt * 16 + 2 * tig;
    float w[4];
    #pragma unroll
    for (int j = 0; j < 4; j++) {
        int k = k0 + (j >> 1) * 8 + (j & 1);
        w[j] = (n < 128) ? W1[(size_t)k * 128 + n]
                         : W1[(size_t)(128 + k) * 128 + (n - 128)];
    }
    int base = ((kt * 32 + nt) * 32 + lane) * 2;
    g_B1u[base]     = packh2(w[0], w[1]);
    g_B1u[base + 1] = packh2(w[2], w[3]);
}

__global__ void prep_B2(const float* __restrict__ W2) {   // [128,128]
    int i = blockIdx.x * blockDim.x + threadIdx.x;
    if (i >= 4096) return;
    int kt = i >> 9, nt = (i >> 5) & 15, lane = i & 31;
    int g = lane >> 2, tig = lane & 3;
    int n = nt * 8 + g;
    int k0 = kt * 16 + 2 * tig;
    float w[4];
    #pragma unroll
    for (int j = 0; j < 4; j++) {
        int k = k0 + (j >> 1) * 8 + (j & 1);
        w[j] = W2[(size_t)k * 128 + n];
    }
    int base = ((kt * 16 + nt) * 32 + lane) * 2;
    g_B2u[base]     = packh2(w[0], w[1]);
    g_B2u[base + 1] = packh2(w[2], w[3]);
}

// ---------------- GEMM1 (mma fp16 2-pass): U(fp16)=x@W1a+b1 ; V(fp16)=x@W1b ----------------
// 8 warps x 16 rows = 128 rows per CTA; N = 256
__global__ __launch_bounds__(256, 2)
void gemm1_kernel(const float* __restrict__ x, const float* __restrict__ b1) {
    extern __shared__ uint32_t sm[];
    uint32_t* sAh = sm;              // 128*68 = 8704
    uint32_t* sAl = sm + 8704;
    const int tid = threadIdx.x;
    const int rbase = blockIdx.x * 128;

    for (int i = tid; i < 128 * 32; i += 256) {
        int r = i >> 5, c4 = i & 31;
        int grow = rbase + r;
        float4 v = (grow < NN) ? ((const float4*)x)[(size_t)grow * 32 + c4]
                               : make_float4(0.f, 0.f, 0.f, 0.f);
        uint32_t h01, l01, h23, l23;
        splitpairh(v.x, v.y, h01, l01);
        splitpairh(v.z, v.w, h23, l23);
        *(uint2*)(sAh + r * APAD + 2 * c4) = make_uint2(h01, h23);
        *(uint2*)(sAl + r * APAD + 2 * c4) = make_uint2(l01, l23);
    }
    __syncthreads();

    const int warp = tid >> 5, lane = tid & 31, g = lane >> 2, tig = lane & 3;
    const uint32_t* a0h = sAh + (warp * 16 + g) * APAD;
    const uint32_t* a1h = sAh + (warp * 16 + g + 8) * APAD;
    const uint32_t* a0l = sAl + (warp * 16 + g) * APAD;
    const uint32_t* a1l = sAl + (warp * 16 + g + 8) * APAD;
    const int row0 = rbase + warp * 16 + g;
    const int row1 = row0 + 8;
    const uint2* gB = (const uint2*)g_B1u;

    for (int nc = 0; nc < 8; nc++) {
        float acc[4][4] = {};
        uint2 bh[4];
        #pragma unroll
        for (int nt = 0; nt < 4; nt++)
            bh[nt] = __ldg(gB + (nc * 4 + nt) * 32 + lane);       // kt = 0
        #pragma unroll
        for (int kt = 0; kt < 8; kt++) {
            uint2 nbh[4];
            if (kt < 7) {
                #pragma unroll
                for (int nt = 0; nt < 4; nt++)
                    nbh[nt] = __ldg(gB + ((kt + 1) * 32 + nc * 4 + nt) * 32 + lane);
            }
            uint32_t ah0 = a0h[kt * 8 + tig], ah1 = a1h[kt * 8 + tig];
            uint32_t ah2 = a0h[kt * 8 + tig + 4], ah3 = a1h[kt * 8 + tig + 4];
            uint32_t al0 = a0l[kt * 8 + tig], al1 = a1l[kt * 8 + tig];
            uint32_t al2 = a0l[kt * 8 + tig + 4], al3 = a1l[kt * 8 + tig + 4];
            #pragma unroll
            for (int nt = 0; nt < 4; nt++) {
                mma_f16(acc[nt], ah0, ah1, ah2, ah3, bh[nt].x, bh[nt].y);
                mma_f16(acc[nt], al0, al1, al2, al3, bh[nt].x, bh[nt].y);
            }
            if (kt < 7) {
                #pragma unroll
                for (int nt = 0; nt < 4; nt++) bh[nt] = nbh[nt];
            }
        }
        #pragma unroll
        for (int nt = 0; nt < 4; nt++) {
            int ncol = (nc * 4 + nt) * 8 + 2 * tig;
            if (ncol < 128) {
                float bb0 = __ldg(b1 + ncol), bb1 = __ldg(b1 + ncol + 1);
                if (row0 < NN)
                    *(__half2*)(g_Uh + (size_t)row0 * H + ncol) =
                        __floats2half2_rn(acc[nt][0] + bb0, acc[nt][1] + bb1);
                if (row1 < NN)
                    *(__half2*)(g_Uh + (size_t)row1 * H + ncol) =
                        __floats2half2_rn(acc[nt][2] + bb0, acc[nt][3] + bb1);
            } else {
                int vc = ncol - 128;
                if (row0 < NN)
                    *(__half2*)(g_Vh + (size_t)row0 * H + vc) =
                        __floats2half2_rn(acc[nt][0], acc[nt][1]);
                if (row1 < NN)
                    *(__half2*)(g_Vh + (size_t)row1 * H + vc) =
                        __floats2half2_rn(acc[nt][2], acc[nt][3]);
            }
        }
    }
}

// ---------------- edge kernel: fp16 U + fp16 V gather, fp32 RED ----------------
__global__ __launch_bounds__(256)
void edge_kernel(const int* __restrict__ ei, const float* __restrict__ ea)
{
    const int lane = threadIdx.x & 31;
    const int gwarp = (blockIdx.x * blockDim.x + threadIdx.x) >> 5;
    const int nwarps = (gridDim.x * blockDim.x) >> 5;

    for (int e0 = gwarp * 4; e0 < NE; e0 += nwarps * 4) {
        int sn[4], dn[4]; float w[4]; uint2 up[4], vp[4];
        int cnt = (NE - e0 < 4) ? (NE - e0) : 4;
        #pragma unroll
        for (int j = 0; j < 4; j++) {
            int e = e0 + j;
            if (j < cnt) { sn[j] = __ldg(ei + e); dn[j] = __ldg(ei + NE + e); w[j] = __ldg(ea + e); }
            else { sn[j] = 0; dn[j] = 0; w[j] = 0.f; }
        }
        #pragma unroll
        for (int j = 0; j < 4; j++) {
            up[j] = *(const uint2*)(g_Uh + (size_t)sn[j] * H + 4 * lane);
            vp[j] = *(const uint2*)(g_Vh + (size_t)dn[j] * H + 4 * lane);
        }
        #pragma unroll
        for (int j = 0; j < 4; j++) {
            if (j < cnt) {
                float2 u0 = __half22float2(*(__half2*)&up[j].x);
                float2 u1 = __half22float2(*(__half2*)&up[j].y);
                float2 v0 = __half22float2(*(__half2*)&vp[j].x);
                float2 v1 = __half22float2(*(__half2*)&vp[j].y);
                float a0 = fmaxf(u0.x + v0.x, 0.f) * w[j];
                float a1 = fmaxf(u0.y + v0.y, 0.f) * w[j];
                float a2 = fmaxf(u1.x + v1.x, 0.f) * w[j];
                float a3 = fmaxf(u1.y + v1.y, 0.f) * w[j];
                float* p = g_S + (size_t)dn[j] * H + 4 * lane;
                asm volatile("red.global.add.v4.f32 [%0], {%1,%2,%3,%4};"
                             :: "l"(p), "f"(a0), "f"(a1), "f"(a2), "f"(a3) : "memory");
                if (lane == 0)
                    asm volatile("red.global.add.f32 [%0], %1;"
                                 :: "l"(g_sumw + dn[j]), "f"(w[j]) : "memory");
            }
        }
    }
}

// ---------------- GEMM2 (mma fp16 2-pass): out = x + S@W2 + b2*sumw ----------------
__global__ __launch_bounds__(256, 2)
void gemm2_kernel(const float* __restrict__ x, const float* __restrict__ b2,
                  float* __restrict__ out) {
    extern __shared__ uint32_t sm[];
    uint32_t* sAh = sm;               // 128*68 = 8704
    uint32_t* sAl = sm + 8704;
    const int tid = threadIdx.x;
    const int rbase = blockIdx.x * 128;

    for (int i = tid; i < 128 * 32; i += 256) {
        int r = i >> 5, c4 = i & 31;
        int grow = rbase + r;
        float4 v = (grow < NN) ? ((const float4*)g_S)[(size_t)grow * 32 + c4]
                               : make_float4(0.f, 0.f, 0.f, 0.f);
        uint32_t h01, l01, h23, l23;
        splitpairh(v.x, v.y, h01, l01);
        splitpairh(v.z, v.w, h23, l23);
        *(uint2*)(sAh + r * APAD + 2 * c4) = make_uint2(h01, h23);
        *(uint2*)(sAl + r * APAD + 2 * c4) = make_uint2(l01, l23);
    }
    __syncthreads();

    const int warp = tid >> 5, lane = tid & 31, g = lane >> 2, tig = lane & 3;
    const uint32_t* a0h = sAh + (warp * 16 + g) * APAD;
    const uint32_t* a1h = sAh + (warp * 16 + g + 8) * APAD;
    const uint32_t* a0l = sAl + (warp * 16 + g) * APAD;
    const uint32_t* a1l = sAl + (warp * 16 + g + 8) * APAD;
    const int row0 = rbase + warp * 16 + g;
    const int row1 = row0 + 8;
    const float sw0 = (row0 < NN) ? g_sumw[row0] : 0.f;
    const float sw1 = (row1 < NN) ? g_sumw[row1] : 0.f;
    const uint2* gB = (const uint2*)g_B2u;

    for (int nc = 0; nc < 4; nc++) {
        float acc[4][4] = {};
        uint2 bh[4];
        #pragma unroll
        for (int nt = 0; nt < 4; nt++)
            bh[nt] = __ldg(gB + (nc * 4 + nt) * 32 + lane);       // kt = 0
        #pragma unroll
        for (int kt = 0; kt < 8; kt++) {
            uint2 nbh[4];
            if (kt < 7) {
                #pragma unroll
                for (int nt = 0; nt < 4; nt++)
                    nbh[nt] = __ldg(gB + ((kt + 1) * 16 + nc * 4 + nt) * 32 + lane);
            }
            uint32_t ah0 = a0h[kt * 8 + tig], ah1 = a1h[kt * 8 + tig];
            uint32_t ah2 = a0h[kt * 8 + tig + 4], ah3 = a1h[kt * 8 + tig + 4];
            uint32_t al0 = a0l[kt * 8 + tig], al1 = a1l[kt * 8 + tig];
            uint32_t al2 = a0l[kt * 8 + tig + 4], al3 = a1l[kt * 8 + tig + 4];
            #pragma unroll
            for (int nt = 0; nt < 4; nt++) {
                mma_f16(acc[nt], ah0, ah1, ah2, ah3, bh[nt].x, bh[nt].y);
                mma_f16(acc[nt], al0, al1, al2, al3, bh[nt].x, bh[nt].y);
            }
            if (kt < 7) {
                #pragma unroll
                for (int nt = 0; nt < 4; nt++) bh[nt] = nbh[nt];
            }
        }
        #pragma unroll
        for (int nt = 0; nt < 4; nt++) {
            int ncol = (nc * 4 + nt) * 8 + 2 * tig;
            float bb0 = __ldg(b2 + ncol), bb1 = __ldg(b2 + ncol + 1);
            if (row0 < NN) {
                float2 xr = *(const float2*)(x + (size_t)row0 * H + ncol);
                *(float2*)(out + (size_t)row0 * H + ncol) =
                    make_float2(xr.x + acc[nt][0] + bb0 * sw0,
                                xr.y + acc[nt][1] + bb1 * sw0);
            }
            if (row1 < NN) {
                float2 xr = *(const float2*)(x + (size_t)row1 * H + ncol);
                *(float2*)(out + (size_t)row1 * H + ncol) =
                    make_float2(xr.x + acc[nt][2] + bb0 * sw1,
                                xr.y + acc[nt][3] + bb1 * sw1);
            }
        }
    }
}

// ---------------- launch ----------------
extern "C" void kernel_launch(void* const* d_in, const int* in_sizes, int n_in,
                              void* d_out, int out_size) {
    (void)in_sizes; (void)n_in; (void)out_size;
    const float* x  = (const float*)d_in[0];
    const int*   ei = (const int*)d_in[1];
    const float* ea = (const float*)d_in[2];
    const float* W1 = (const float*)d_in[3];
    const float* b1 = (const float*)d_in[4];
    const float* W2 = (const float*)d_in[5];
    const float* b2 = (const float*)d_in[6];
    float* out = (float*)d_out;

    const int nz = NN * H / 4 + NN / 4;
    zero_kernel<<<(nz + 255) / 256, 256>>>();
    prep_B1<<<32, 256>>>(W1);
    prep_B2<<<16, 256>>>(W2);

    const size_t smemA = (size_t)(2 * 8704) * 4;        // 68 KB (A hi/lo)
    cudaFuncSetAttribute(gemm1_kernel, cudaFuncAttributeMaxDynamicSharedMemorySize, (int)smemA);
    gemm1_kernel<<<(NN + 127) / 128, 256, smemA>>>(x, b1);   // launch #4 -> profiled

    edge_kernel<<<2048, 256>>>(ei, ea);

    cudaFuncSetAttribute(gemm2_kernel, cudaFuncAttributeMaxDynamicSharedMemorySize, (int)smemA);
    gemm2_kernel<<<(NN + 127) / 128, 256, smemA>>>(x, b2, out);
}